// round 11
// baseline (speedup 1.0000x reference)
#include <cuda_runtime.h>
#include <math.h>

#define FD 256
#define NMAX 50048
#define EMAX 800000

// ------------------------- scratch (device globals, per-branch) ------------
__device__ float  g_bufA[2][NMAX * FD];
__device__ float  g_bufB[2][NMAX * FD];
__device__ int    g_deg[2][NMAX];
__device__ int    g_rowptr[2][NMAX + 1];
__device__ int    g_offs[2][NMAX];
__device__ int    g_sorted[2][EMAX];

__device__ float  g_tmpv[2][NMAX];
__device__ float  g_d2v[2][NMAX];
__device__ float  g_d4v[2][NMAX];

__device__ float  g_G[2][FD * FD];
__device__ float  g_colsum[2][FD];
__device__ float  g_scale[2][FD];
__device__ float  g_c[2][FD];
__device__ float  g_Ps[2][FD * FD];
__device__ float  g_Q[2][FD * FD];
__device__ float  g_Zg[2][FD * FD];
__device__ float  g_u4[2][FD];

// shared
__device__ float  g_P[FD * FD];             // W3 @ W2
__device__ float  g_W1T[FD * FD];
__device__ float  g_v3[FD];                 // W3 @ b2

// ------------------------- packed f32x2 helpers ----------------------------
__device__ __forceinline__ double pack2(float lo, float hi) {
    double d;
    asm("mov.b64 %0, {%1, %2};" : "=d"(d) : "f"(lo), "f"(hi));
    return d;
}
__device__ __forceinline__ void unpack2(double d, float& lo, float& hi) {
    asm("mov.b64 {%0, %1}, %2;" : "=f"(lo), "=f"(hi) : "d"(d));
}
__device__ __forceinline__ double ffma2(double a, double b, double c) {
    double d;
    asm("fma.rn.f32x2 %0, %1, %2, %3;" : "=d"(d) : "d"(a), "d"(b), "d"(c));
    return d;
}

// ------------------------- CSR construction -------------------------------
__global__ void hist_kernel(int* __restrict__ deg, const int* __restrict__ dst, int E) {
    int e = blockIdx.x * blockDim.x + threadIdx.x;
    if (e < E) atomicAdd(&deg[dst[e]], 1);
}

__global__ void scan_kernel(const int* __restrict__ deg, int* __restrict__ rowptr,
                            int* __restrict__ offs, int n) {
    __shared__ int s[1024];
    int t = threadIdx.x;
    int chunk = (n + 1023) >> 10;
    int lo = t * chunk; if (lo > n) lo = n;
    int hi = lo + chunk; if (hi > n) hi = n;
    int sum = 0;
    for (int i = lo; i < hi; i++) sum += deg[i];
    s[t] = sum;
    __syncthreads();
    for (int d = 1; d < 1024; d <<= 1) {
        int v = (t >= d) ? s[t - d] : 0;
        __syncthreads();
        s[t] += v;
        __syncthreads();
    }
    int run = s[t] - sum;
    for (int i = lo; i < hi; i++) {
        rowptr[i] = run;
        offs[i]   = run;
        run += deg[i];
    }
    if (t == 1023) rowptr[n] = s[1023];
}

__global__ void scatter_kernel(int* __restrict__ offs, int* __restrict__ sorted,
                               const int* __restrict__ src, const int* __restrict__ dst, int E) {
    int e = blockIdx.x * blockDim.x + threadIdx.x;
    if (e < E) {
        int p = atomicAdd(&offs[dst[e]], 1);
        sorted[p] = src[e];
    }
}

// ------------------------- SpMV chain (d vectors) --------------------------
__global__ void spmv_deg_kernel(const int* __restrict__ rowptr, const int* __restrict__ sorted,
                                float* __restrict__ y, int n) {
    int i = blockIdx.x * blockDim.x + threadIdx.x;
    if (i >= n) return;
    int s = rowptr[i], e = rowptr[i + 1];
    float acc = 0.f;
    for (int k = s; k < e; k++) {
        int u = sorted[k];
        acc += (float)(rowptr[u + 1] - rowptr[u]);
    }
    y[i] = acc;
}

__global__ void spmv_kernel(const int* __restrict__ rowptr, const int* __restrict__ sorted,
                            const float* __restrict__ x, float* __restrict__ y, int n) {
    int i = blockIdx.x * blockDim.x + threadIdx.x;
    if (i >= n) return;
    int s = rowptr[i], e = rowptr[i + 1];
    float acc = 0.f;
    for (int k = s; k < e; k++) acc += x[sorted[k]];
    y[i] = acc;
}

// ------------------------- SpMM (pull, CSR, warp per node) -----------------
// block = (32, 8): one warp per node, each lane owns 8 features (2 float4)
// 8-edge unroll for 16 outstanding LDG.128 per lane; L1 bypassed (__ldcg)
__global__ __launch_bounds__(256, 2)
void spmm_kernel(const int* __restrict__ rowptr, const int* __restrict__ sorted,
                 const float* __restrict__ h, float* __restrict__ out, int n) {
    int lane = threadIdx.x;
    int node = blockIdx.x * 8 + threadIdx.y;
    if (node >= n) return;
    int s = rowptr[node];
    int e = rowptr[node + 1];
    const float4* hp = (const float4*)h;
    float4 acc0 = make_float4(0.f, 0.f, 0.f, 0.f);
    float4 acc1 = make_float4(0.f, 0.f, 0.f, 0.f);
    int i = s;
    for (; i + 8 <= e; i += 8) {
        int u[8];
#pragma unroll
        for (int t = 0; t < 8; t++) u[t] = sorted[i + t];
        float4 va[8], vb[8];
#pragma unroll
        for (int t = 0; t < 8; t++) {
            va[t] = __ldcg(&hp[(size_t)u[t] * 64 + lane]);
            vb[t] = __ldcg(&hp[(size_t)u[t] * 64 + 32 + lane]);
        }
#pragma unroll
        for (int t = 0; t < 8; t++) {
            acc0.x += va[t].x; acc0.y += va[t].y; acc0.z += va[t].z; acc0.w += va[t].w;
            acc1.x += vb[t].x; acc1.y += vb[t].y; acc1.z += vb[t].z; acc1.w += vb[t].w;
        }
    }
    if (i + 4 <= e) {
        int u[4];
#pragma unroll
        for (int t = 0; t < 4; t++) u[t] = sorted[i + t];
        float4 va[4], vb[4];
#pragma unroll
        for (int t = 0; t < 4; t++) {
            va[t] = __ldcg(&hp[(size_t)u[t] * 64 + lane]);
            vb[t] = __ldcg(&hp[(size_t)u[t] * 64 + 32 + lane]);
        }
#pragma unroll
        for (int t = 0; t < 4; t++) {
            acc0.x += va[t].x; acc0.y += va[t].y; acc0.z += va[t].z; acc0.w += va[t].w;
            acc1.x += vb[t].x; acc1.y += vb[t].y; acc1.z += vb[t].z; acc1.w += vb[t].w;
        }
        i += 4;
    }
    for (; i < e; i++) {
        int u = sorted[i];
        float4 a = __ldcg(&hp[(size_t)u * 64 + lane]);
        float4 b = __ldcg(&hp[(size_t)u * 64 + 32 + lane]);
        acc0.x += a.x; acc0.y += a.y; acc0.z += a.z; acc0.w += a.w;
        acc1.x += b.x; acc1.y += b.y; acc1.z += b.z; acc1.w += b.w;
    }
    float4* op = (float4*)&out[(size_t)node * FD];
    op[lane]      = acc0;
    op[lane + 32] = acc1;
}

// --------- NT GEMM: C = H @ W^T + bias + d4*u4^T + d2*u2^T -----------------
__global__ __launch_bounds__(256, 2)
void gemm_nt2_kernel(const float* __restrict__ H, const float* __restrict__ W,
                     const float* __restrict__ bias,
                     const float* __restrict__ d4, const float* __restrict__ u4,
                     const float* __restrict__ d2, const float* __restrict__ u2,
                     float* __restrict__ C, int M) {
    __shared__ float As[16][132];
    __shared__ float Bs[16][132];
    int tid = threadIdx.x;
    int tx = tid & 15;
    int ty = tid >> 4;
    int bm = blockIdx.x * 128;
    int bn = blockIdx.y * 128;

    double accp[8][4];
#pragma unroll
    for (int i = 0; i < 8; i++)
#pragma unroll
        for (int j = 0; j < 4; j++) accp[i][j] = 0.0;

    for (int k0 = 0; k0 < 256; k0 += 16) {
#pragma unroll
        for (int l = 0; l < 2; l++) {
            int id = l * 256 + tid;
            int row = id >> 2, c4 = id & 3;
            int gr = bm + row;
            float4 v = (gr < M) ? *(const float4*)&H[(size_t)gr * 256 + k0 + c4 * 4]
                                : make_float4(0.f, 0.f, 0.f, 0.f);
            As[c4 * 4 + 0][row] = v.x;
            As[c4 * 4 + 1][row] = v.y;
            As[c4 * 4 + 2][row] = v.z;
            As[c4 * 4 + 3][row] = v.w;
        }
#pragma unroll
        for (int l = 0; l < 2; l++) {
            int id = l * 256 + tid;
            int row = id >> 2, c4 = id & 3;
            float4 v = *(const float4*)&W[(size_t)(bn + row) * 256 + k0 + c4 * 4];
            Bs[c4 * 4 + 0][row] = v.x;
            Bs[c4 * 4 + 1][row] = v.y;
            Bs[c4 * 4 + 2][row] = v.z;
            Bs[c4 * 4 + 3][row] = v.w;
        }
        __syncthreads();
#pragma unroll
        for (int kk = 0; kk < 16; kk++) {
            float4 a0 = *(const float4*)&As[kk][ty * 8];
            float4 a1 = *(const float4*)&As[kk][ty * 8 + 4];
            const double* b2p = (const double*)&Bs[kk][tx * 8];
            double pb0 = b2p[0], pb1 = b2p[1], pb2 = b2p[2], pb3 = b2p[3];
            double pa[8];
            pa[0] = pack2(a0.x, a0.x); pa[1] = pack2(a0.y, a0.y);
            pa[2] = pack2(a0.z, a0.z); pa[3] = pack2(a0.w, a0.w);
            pa[4] = pack2(a1.x, a1.x); pa[5] = pack2(a1.y, a1.y);
            pa[6] = pack2(a1.z, a1.z); pa[7] = pack2(a1.w, a1.w);
#pragma unroll
            for (int i = 0; i < 8; i++) {
                accp[i][0] = ffma2(pa[i], pb0, accp[i][0]);
                accp[i][1] = ffma2(pa[i], pb1, accp[i][1]);
                accp[i][2] = ffma2(pa[i], pb2, accp[i][2]);
                accp[i][3] = ffma2(pa[i], pb3, accp[i][3]);
            }
        }
        __syncthreads();
    }

    float bv[8], u4v[8], u2v[8];
#pragma unroll
    for (int j = 0; j < 8; j++) {
        bv[j]  = bias[bn + tx * 8 + j];
        u4v[j] = u4[bn + tx * 8 + j];
        u2v[j] = u2[bn + tx * 8 + j];
    }
#pragma unroll
    for (int i = 0; i < 8; i++) {
        int gr = bm + ty * 8 + i;
        if (gr < M) {
            float c[8];
#pragma unroll
            for (int j = 0; j < 4; j++) unpack2(accp[i][j], c[2 * j], c[2 * j + 1]);
            float dv4 = d4[gr], dv2 = d2[gr];
#pragma unroll
            for (int j = 0; j < 8; j++)
                c[j] = c[j] + bv[j] + dv4 * u4v[j] + dv2 * u2v[j];
            *(float4*)&C[(size_t)gr * 256 + bn + tx * 8]     = make_float4(c[0], c[1], c[2], c[3]);
            *(float4*)&C[(size_t)gr * 256 + bn + tx * 8 + 4] = make_float4(c[4], c[5], c[6], c[7]);
        }
    }
}

// ------------------------- column sums -------------------------------------
__global__ void colsum_kernel(const float* __restrict__ h, float* __restrict__ colsum, int n) {
    int f = threadIdx.x;
    int r0 = blockIdx.x * 512;
    int r1 = r0 + 512; if (r1 > n) r1 = n;
    float s = 0.f;
    for (int r = r0; r < r1; r++) s += h[(size_t)r * FD + f];
    atomicAdd(&colsum[f], s);
}

// ------------------------- small 256x256 ops -------------------------------
__global__ void transpose_kernel(const float* __restrict__ A, float* __restrict__ AT) {
    __shared__ float t[32][33];
    int bx = blockIdx.x * 32, by = blockIdx.y * 32;
    t[threadIdx.y][threadIdx.x] = A[(by + threadIdx.y) * FD + bx + threadIdx.x];
    __syncthreads();
    AT[(bx + threadIdx.y) * FD + by + threadIdx.x] = t[threadIdx.x][threadIdx.y];
}

__global__ void nn_kernel(const float* __restrict__ A, const float* __restrict__ B,
                          float* __restrict__ C) {
    __shared__ float a[FD];
    int k = blockIdx.x, j = threadIdx.x;
    a[j] = A[k * FD + j];
    __syncthreads();
    float s = 0.f;
#pragma unroll 8
    for (int p = 0; p < FD; p++) s += a[p] * B[p * FD + j];
    C[k * FD + j] = s;
}

__global__ void rowvec_kernel(const float* __restrict__ W, const float* __restrict__ x,
                              float* __restrict__ y) {
    __shared__ float sx[FD];
    int j = threadIdx.x;
    sx[j] = x[j];
    __syncthreads();
    float s = 0.f;
#pragma unroll 8
    for (int p = 0; p < FD; p++) s += W[j * FD + p] * sx[p];
    y[j] = s;
}

// BN affine from Gram
__global__ void bn_kernel(const float* __restrict__ W1, const float* __restrict__ b1,
                          const float* __restrict__ gamma, const float* __restrict__ beta,
                          const float* __restrict__ Zg, const float* __restrict__ colsum,
                          float* __restrict__ scale, float* __restrict__ cvec, int n) {
    __shared__ double rq[256], rt[256];
    int j = blockIdx.x;
    int p = threadIdx.x;
    double w = (double)W1[j * FD + p];
    rq[p] = w * (double)Zg[p * FD + j];
    rt[p] = w * ((double)colsum[p] / (double)n);
    __syncthreads();
    for (int d = 128; d > 0; d >>= 1) {
        if (p < d) { rq[p] += rq[p + d]; rt[p] += rt[p + d]; }
        __syncthreads();
    }
    if (p == 0) {
        double tm   = rt[0];
        double var  = rq[0] / (double)n - tm * tm;
        double mean = tm + (double)b1[j];
        double sc   = (double)gamma[j] / sqrt(var + 1e-5);
        double sh   = (double)beta[j] - mean * sc;
        scale[j] = (float)sc;
        cvec[j]  = (float)((double)b1[j] * sc + sh);
    }
}

__global__ void scalecols_kernel(const float* __restrict__ P, const float* __restrict__ scale,
                                 float* __restrict__ Ps) {
    int k = blockIdx.x, j = threadIdx.x;
    Ps[k * FD + j] = P[k * FD + j] * scale[j];
}

// ------------------ TN GEMM: out += H1^T @ H2 (split-K, atomics) -----------
__global__ __launch_bounds__(256, 2)
void gemm_tn_kernel(const float* __restrict__ H1, const float* __restrict__ H2,
                    float* __restrict__ out, int M, int chunk) {
    __shared__ float S1[16][132];
    __shared__ float S2[16][68];
    int tid = threadIdx.x;
    int tx = tid & 15, ty = tid >> 4;
    int ba = blockIdx.x * 128;
    int bb = blockIdx.y * 64;
    int k0 = blockIdx.z * chunk;
    int k1 = k0 + chunk; if (k1 > M) k1 = M;

    double accp[8][2];
#pragma unroll
    for (int i = 0; i < 8; i++) { accp[i][0] = 0.0; accp[i][1] = 0.0; }

    for (int k = k0; k < k1; k += 16) {
#pragma unroll
        for (int l = 0; l < 2; l++) {
            int id = l * 256 + tid;
            int row = id >> 5, c = id & 31;
            int gk = k + row;
            float4 v = (gk < k1) ? *(const float4*)&H1[(size_t)gk * FD + ba + c * 4]
                                 : make_float4(0.f, 0.f, 0.f, 0.f);
            *(float4*)&S1[row][c * 4] = v;
        }
        {
            int row = tid >> 4, c = tid & 15;
            int gk = k + row;
            float4 v = (gk < k1) ? *(const float4*)&H2[(size_t)gk * FD + bb + c * 4]
                                 : make_float4(0.f, 0.f, 0.f, 0.f);
            *(float4*)&S2[row][c * 4] = v;
        }
        __syncthreads();
#pragma unroll
        for (int kk = 0; kk < 16; kk++) {
            float4 a0 = *(const float4*)&S1[kk][ty * 8];
            float4 a1 = *(const float4*)&S1[kk][ty * 8 + 4];
            const double* b2p = (const double*)&S2[kk][tx * 4];
            double pb0 = b2p[0], pb1 = b2p[1];
            double pa[8];
            pa[0] = pack2(a0.x, a0.x); pa[1] = pack2(a0.y, a0.y);
            pa[2] = pack2(a0.z, a0.z); pa[3] = pack2(a0.w, a0.w);
            pa[4] = pack2(a1.x, a1.x); pa[5] = pack2(a1.y, a1.y);
            pa[6] = pack2(a1.z, a1.z); pa[7] = pack2(a1.w, a1.w);
#pragma unroll
            for (int i = 0; i < 8; i++) {
                accp[i][0] = ffma2(pa[i], pb0, accp[i][0]);
                accp[i][1] = ffma2(pa[i], pb1, accp[i][1]);
            }
        }
        __syncthreads();
    }
#pragma unroll
    for (int i = 0; i < 8; i++) {
        float c0, c1, c2, c3;
        unpack2(accp[i][0], c0, c1);
        unpack2(accp[i][1], c2, c3);
        float* o = &out[(size_t)(ba + ty * 8 + i) * FD + bb + tx * 4];
        atomicAdd(o + 0, c0);
        atomicAdd(o + 1, c1);
        atomicAdd(o + 2, c2);
        atomicAdd(o + 3, c3);
    }
}

// ------------------------- per-branch pointer bundle -----------------------
struct BranchPtrs {
    int *deg, *rowptr, *offs, *sorted;
    float *A, *B, *tmp, *d2, *d4;
    float *G, *colsum, *scale, *cvec, *Ps, *Q, *Zg, *u4;
};

// ------------------------- orchestration -----------------------------------
extern "C" void kernel_launch(void* const* d_in, const int* in_sizes, int n_in,
                              void* d_out, int out_size) {
    const float* X       = (const float*)d_in[0];
    const int*   srcs[2] = {(const int*)d_in[1], (const int*)d_in[3]};
    const int*   dsts[2] = {(const int*)d_in[2], (const int*)d_in[4]};
    const float* W[3]    = {(const float*)d_in[5], (const float*)d_in[7], (const float*)d_in[9]};
    const float* bias[3] = {(const float*)d_in[6], (const float*)d_in[8], (const float*)d_in[10]};
    const float* gamma   = (const float*)d_in[11];
    const float* beta    = (const float*)d_in[12];
    (void)n_in;

    int n = in_sizes[0] / FD;
    int E = in_sizes[1];
    float* out = (float*)d_out;

    // resolve symbol addresses
    float *pP, *pW1T, *pV3;
    cudaGetSymbolAddress((void**)&pP, g_P);
    cudaGetSymbolAddress((void**)&pW1T, g_W1T);
    cudaGetSymbolAddress((void**)&pV3, g_v3);

    BranchPtrs bp[2];
    {
        int *deg, *rowptr, *offs, *sorted;
        float *A, *B, *tmp, *d2, *d4, *G, *colsum, *scale, *cvec, *Ps, *Q, *Zg, *u4;
        cudaGetSymbolAddress((void**)&deg, g_deg);
        cudaGetSymbolAddress((void**)&rowptr, g_rowptr);
        cudaGetSymbolAddress((void**)&offs, g_offs);
        cudaGetSymbolAddress((void**)&sorted, g_sorted);
        cudaGetSymbolAddress((void**)&A, g_bufA);
        cudaGetSymbolAddress((void**)&B, g_bufB);
        cudaGetSymbolAddress((void**)&tmp, g_tmpv);
        cudaGetSymbolAddress((void**)&d2, g_d2v);
        cudaGetSymbolAddress((void**)&d4, g_d4v);
        cudaGetSymbolAddress((void**)&G, g_G);
        cudaGetSymbolAddress((void**)&colsum, g_colsum);
        cudaGetSymbolAddress((void**)&scale, g_scale);
        cudaGetSymbolAddress((void**)&cvec, g_c);
        cudaGetSymbolAddress((void**)&Ps, g_Ps);
        cudaGetSymbolAddress((void**)&Q, g_Q);
        cudaGetSymbolAddress((void**)&Zg, g_Zg);
        cudaGetSymbolAddress((void**)&u4, g_u4);
        for (int b = 0; b < 2; b++) {
            bp[b].deg = deg + b * NMAX;
            bp[b].rowptr = rowptr + b * (NMAX + 1);
            bp[b].offs = offs + b * NMAX;
            bp[b].sorted = sorted + b * EMAX;
            bp[b].A = A + (size_t)b * NMAX * FD;
            bp[b].B = B + (size_t)b * NMAX * FD;
            bp[b].tmp = tmp + b * NMAX;
            bp[b].d2 = d2 + b * NMAX;
            bp[b].d4 = d4 + b * NMAX;
            bp[b].G = G + b * FD * FD;
            bp[b].colsum = colsum + b * FD;
            bp[b].scale = scale + b * FD;
            bp[b].cvec = cvec + b * FD;
            bp[b].Ps = Ps + b * FD * FD;
            bp[b].Q = Q + b * FD * FD;
            bp[b].Zg = Zg + b * FD * FD;
            bp[b].u4 = u4 + b * FD;
        }
    }

    // streams / events (created once; handles only, no device memory)
    static cudaStream_t s1 = nullptr;
    static cudaEvent_t eFork = nullptr, eJoin = nullptr;
    if (!s1) {
        cudaStreamCreateWithFlags(&s1, cudaStreamNonBlocking);
        cudaEventCreateWithFlags(&eFork, cudaEventDisableTiming);
        cudaEventCreateWithFlags(&eJoin, cudaEventDisableTiming);
    }

    dim3 spmmBlock(32, 8);
    int  spmmGrid = (n + 7) / 8;
    int  eGrid = (E + 255) / 256;
    int  nGrid256 = (n + 255) / 256;
    int  redGrid = (n + 511) / 512;
    dim3 ntGrid((n + 127) / 128, FD / 128);
    int  chunk = 2048;
    dim3 tnGrid(FD / 128, FD / 64, (n + chunk - 1) / chunk);
    dim3 tpGrid(FD / 32, FD / 32), tpBlock(32, 32);

    // shared precompute on capture stream
    nn_kernel<<<FD, FD>>>(W[2], W[1], pP);
    rowvec_kernel<<<1, FD>>>(W[2], bias[1], pV3);
    transpose_kernel<<<tpGrid, tpBlock>>>(W[0], pW1T);

    // fork branch 1 onto s1
    cudaEventRecord(eFork, 0);
    cudaStreamWaitEvent(s1, eFork, 0);

    for (int br = 0; br < 2; ++br) {
        cudaStream_t st = (br == 0) ? (cudaStream_t)0 : s1;
        BranchPtrs& p = bp[br];

        // CSR build (counting sort by dst)
        cudaMemsetAsync(p.deg, 0, n * sizeof(int), st);
        hist_kernel<<<eGrid, 256, 0, st>>>(p.deg, dsts[br], E);
        scan_kernel<<<1, 1024, 0, st>>>(p.deg, p.rowptr, p.offs, n);
        scatter_kernel<<<eGrid, 256, 0, st>>>(p.offs, p.sorted, srcs[br], dsts[br], E);

        // d2 = A^2 1 ; d4 = A^4 1
        spmv_deg_kernel<<<nGrid256, 256, 0, st>>>(p.rowptr, p.sorted, p.d2, n);
        spmv_kernel<<<nGrid256, 256, 0, st>>>(p.rowptr, p.sorted, p.d2, p.tmp, n);
        spmv_kernel<<<nGrid256, 256, 0, st>>>(p.rowptr, p.sorted, p.tmp, p.d4, n);

        // Z2 = A^2 X
        spmm_kernel<<<spmmGrid, spmmBlock, 0, st>>>(p.rowptr, p.sorted, X, p.A, n);
        spmm_kernel<<<spmmGrid, spmmBlock, 0, st>>>(p.rowptr, p.sorted, p.A, p.B, n);

        // stats of Z2: column sums + Gram
        cudaMemsetAsync(p.colsum, 0, FD * sizeof(float), st);
        colsum_kernel<<<redGrid, 256, 0, st>>>(p.B, p.colsum, n);
        cudaMemsetAsync(p.G, 0, FD * FD * sizeof(float), st);
        gemm_tn_kernel<<<tnGrid, 256, 0, st>>>(p.B, p.B, p.G, n, chunk);

        // BN affine coefficients from Gram
        nn_kernel<<<FD, FD, 0, st>>>(p.G, pW1T, p.Zg);
        bn_kernel<<<FD, FD, 0, st>>>(W[0], bias[0], gamma, beta, p.Zg, p.colsum,
                                     p.scale, p.cvec, n);

        // Q = P diag(s) W1 ; u4 = P c
        scalecols_kernel<<<FD, FD, 0, st>>>(pP, p.scale, p.Ps);
        nn_kernel<<<FD, FD, 0, st>>>(p.Ps, W[0], p.Q);
        rowvec_kernel<<<1, FD, 0, st>>>(pP, p.cvec, p.u4);

        // Z6 = A^4 Z2
        spmm_kernel<<<spmmGrid, spmmBlock, 0, st>>>(p.rowptr, p.sorted, p.B, p.A, n);
        spmm_kernel<<<spmmGrid, spmmBlock, 0, st>>>(p.rowptr, p.sorted, p.A, p.B, n);
        spmm_kernel<<<spmmGrid, spmmBlock, 0, st>>>(p.rowptr, p.sorted, p.B, p.A, n);
        spmm_kernel<<<spmmGrid, spmmBlock, 0, st>>>(p.rowptr, p.sorted, p.A, p.B, n);

        // h3 = Z6 Q^T + d4 u4^T + d2 v3^T + b3   (into p.A)
        gemm_nt2_kernel<<<ntGrid, 256, 0, st>>>(p.B, p.Q, bias[2], p.d4, p.u4,
                                                p.d2, pV3, p.A, n);
    }

    // join branch 1 back into capture stream
    cudaEventRecord(eJoin, s1);
    cudaStreamWaitEvent(0, eJoin, 0);

    // out = h3a^T @ h3b
    cudaMemsetAsync(out, 0, (size_t)out_size * sizeof(float));
    gemm_tn_kernel<<<tnGrid, 256>>>(bp[0].A, bp[1].A, out, n, chunk);
}

// round 12
// speedup vs baseline: 1.1289x; 1.1289x over previous
#include <cuda_runtime.h>
#include <math.h>

#define FD 256
#define NMAX 50048
#define EMAX 800000

// ------------------------- scratch (device globals, per-branch) ------------
__device__ float  g_bufA[2][NMAX * FD];
__device__ float  g_bufB[2][NMAX * FD];
__device__ int    g_deg[2][NMAX];
__device__ int    g_rowptr[2][NMAX + 1];
__device__ int    g_offs[2][NMAX];
__device__ int    g_sorted[2][EMAX];

__device__ float  g_tmpv[2][NMAX];
__device__ float  g_d2v[2][NMAX];
__device__ float  g_d4v[2][NMAX];

__device__ float  g_G[2][FD * FD];
__device__ float  g_colsum[2][FD];
__device__ float  g_scale[2][FD];
__device__ float  g_c[2][FD];
__device__ float  g_Ps[2][FD * FD];
__device__ float  g_Q[2][FD * FD];
__device__ float  g_Zg[2][FD * FD];
__device__ float  g_u4[2][FD];

// shared
__device__ float  g_P[FD * FD];             // W3 @ W2
__device__ float  g_W1T[FD * FD];
__device__ float  g_v3[FD];                 // W3 @ b2

// ------------------------- packed f32x2 helpers ----------------------------
__device__ __forceinline__ double pack2(float lo, float hi) {
    double d;
    asm("mov.b64 %0, {%1, %2};" : "=d"(d) : "f"(lo), "f"(hi));
    return d;
}
__device__ __forceinline__ void unpack2(double d, float& lo, float& hi) {
    asm("mov.b64 {%0, %1}, %2;" : "=f"(lo), "=f"(hi) : "d"(d));
}
__device__ __forceinline__ double ffma2(double a, double b, double c) {
    double d;
    asm("fma.rn.f32x2 %0, %1, %2, %3;" : "=d"(d) : "d"(a), "d"(b), "d"(c));
    return d;
}

// ------------------------- CSR construction -------------------------------
__global__ void hist_kernel(int* __restrict__ deg, const int* __restrict__ dst, int E) {
    int e = blockIdx.x * blockDim.x + threadIdx.x;
    if (e < E) atomicAdd(&deg[dst[e]], 1);
}

__global__ void scan_kernel(const int* __restrict__ deg, int* __restrict__ rowptr,
                            int* __restrict__ offs, int n) {
    __shared__ int s[1024];
    int t = threadIdx.x;
    int chunk = (n + 1023) >> 10;
    int lo = t * chunk; if (lo > n) lo = n;
    int hi = lo + chunk; if (hi > n) hi = n;
    int sum = 0;
    for (int i = lo; i < hi; i++) sum += deg[i];
    s[t] = sum;
    __syncthreads();
    for (int d = 1; d < 1024; d <<= 1) {
        int v = (t >= d) ? s[t - d] : 0;
        __syncthreads();
        s[t] += v;
        __syncthreads();
    }
    int run = s[t] - sum;
    for (int i = lo; i < hi; i++) {
        rowptr[i] = run;
        offs[i]   = run;
        run += deg[i];
    }
    if (t == 1023) rowptr[n] = s[1023];
}

__global__ void scatter_kernel(int* __restrict__ offs, int* __restrict__ sorted,
                               const int* __restrict__ src, const int* __restrict__ dst, int E) {
    int e = blockIdx.x * blockDim.x + threadIdx.x;
    if (e < E) {
        int p = atomicAdd(&offs[dst[e]], 1);
        sorted[p] = src[e];
    }
}

// ------------------------- SpMV chain (d vectors) --------------------------
__global__ void spmv_deg_kernel(const int* __restrict__ rowptr, const int* __restrict__ sorted,
                                float* __restrict__ y, int n) {
    int i = blockIdx.x * blockDim.x + threadIdx.x;
    if (i >= n) return;
    int s = rowptr[i], e = rowptr[i + 1];
    float acc = 0.f;
    for (int k = s; k < e; k++) {
        int u = sorted[k];
        acc += (float)(rowptr[u + 1] - rowptr[u]);
    }
    y[i] = acc;
}

__global__ void spmv_kernel(const int* __restrict__ rowptr, const int* __restrict__ sorted,
                            const float* __restrict__ x, float* __restrict__ y, int n) {
    int i = blockIdx.x * blockDim.x + threadIdx.x;
    if (i >= n) return;
    int s = rowptr[i], e = rowptr[i + 1];
    float acc = 0.f;
    for (int k = s; k < e; k++) acc += x[sorted[k]];
    y[i] = acc;
}

// ------------------------- SpMM (pull, CSR, warp per node) -----------------
// block = (32, 8): one warp per node, each lane owns 8 features (2 float4)
__global__ void spmm_kernel(const int* __restrict__ rowptr, const int* __restrict__ sorted,
                            const float* __restrict__ h, float* __restrict__ out, int n) {
    int lane = threadIdx.x;
    int node = blockIdx.x * 8 + threadIdx.y;
    if (node >= n) return;
    int s = rowptr[node];
    int e = rowptr[node + 1];
    const float4* hp = (const float4*)h;
    float4 acc0 = make_float4(0.f, 0.f, 0.f, 0.f);
    float4 acc1 = make_float4(0.f, 0.f, 0.f, 0.f);
    int i = s;
    for (; i + 4 <= e; i += 4) {
        int u0 = sorted[i];
        int u1 = sorted[i + 1];
        int u2 = sorted[i + 2];
        int u3 = sorted[i + 3];
        float4 a0 = __ldg(&hp[(size_t)u0 * 64 + lane]);
        float4 b0 = __ldg(&hp[(size_t)u0 * 64 + 32 + lane]);
        float4 a1 = __ldg(&hp[(size_t)u1 * 64 + lane]);
        float4 b1 = __ldg(&hp[(size_t)u1 * 64 + 32 + lane]);
        float4 a2 = __ldg(&hp[(size_t)u2 * 64 + lane]);
        float4 b2 = __ldg(&hp[(size_t)u2 * 64 + 32 + lane]);
        float4 a3 = __ldg(&hp[(size_t)u3 * 64 + lane]);
        float4 b3 = __ldg(&hp[(size_t)u3 * 64 + 32 + lane]);
        acc0.x += (a0.x + a1.x) + (a2.x + a3.x);
        acc0.y += (a0.y + a1.y) + (a2.y + a3.y);
        acc0.z += (a0.z + a1.z) + (a2.z + a3.z);
        acc0.w += (a0.w + a1.w) + (a2.w + a3.w);
        acc1.x += (b0.x + b1.x) + (b2.x + b3.x);
        acc1.y += (b0.y + b1.y) + (b2.y + b3.y);
        acc1.z += (b0.z + b1.z) + (b2.z + b3.z);
        acc1.w += (b0.w + b1.w) + (b2.w + b3.w);
    }
    for (; i < e; i++) {
        int u = sorted[i];
        float4 a = __ldg(&hp[(size_t)u * 64 + lane]);
        float4 b = __ldg(&hp[(size_t)u * 64 + 32 + lane]);
        acc0.x += a.x; acc0.y += a.y; acc0.z += a.z; acc0.w += a.w;
        acc1.x += b.x; acc1.y += b.y; acc1.z += b.z; acc1.w += b.w;
    }
    float4* op = (float4*)&out[(size_t)node * FD];
    op[lane]      = acc0;
    op[lane + 32] = acc1;
}

// --------- NT GEMM: C = H @ W^T + bias + d4*u4^T + d2*u2^T -----------------
__global__ __launch_bounds__(256, 2)
void gemm_nt2_kernel(const float* __restrict__ H, const float* __restrict__ W,
                     const float* __restrict__ bias,
                     const float* __restrict__ d4, const float* __restrict__ u4,
                     const float* __restrict__ d2, const float* __restrict__ u2,
                     float* __restrict__ C, int M) {
    __shared__ float As[16][132];
    __shared__ float Bs[16][132];
    int tid = threadIdx.x;
    int tx = tid & 15;
    int ty = tid >> 4;
    int bm = blockIdx.x * 128;
    int bn = blockIdx.y * 128;

    double accp[8][4];
#pragma unroll
    for (int i = 0; i < 8; i++)
#pragma unroll
        for (int j = 0; j < 4; j++) accp[i][j] = 0.0;

    for (int k0 = 0; k0 < 256; k0 += 16) {
#pragma unroll
        for (int l = 0; l < 2; l++) {
            int id = l * 256 + tid;
            int row = id >> 2, c4 = id & 3;
            int gr = bm + row;
            float4 v = (gr < M) ? *(const float4*)&H[(size_t)gr * 256 + k0 + c4 * 4]
                                : make_float4(0.f, 0.f, 0.f, 0.f);
            As[c4 * 4 + 0][row] = v.x;
            As[c4 * 4 + 1][row] = v.y;
            As[c4 * 4 + 2][row] = v.z;
            As[c4 * 4 + 3][row] = v.w;
        }
#pragma unroll
        for (int l = 0; l < 2; l++) {
            int id = l * 256 + tid;
            int row = id >> 2, c4 = id & 3;
            float4 v = *(const float4*)&W[(size_t)(bn + row) * 256 + k0 + c4 * 4];
            Bs[c4 * 4 + 0][row] = v.x;
            Bs[c4 * 4 + 1][row] = v.y;
            Bs[c4 * 4 + 2][row] = v.z;
            Bs[c4 * 4 + 3][row] = v.w;
        }
        __syncthreads();
#pragma unroll
        for (int kk = 0; kk < 16; kk++) {
            float4 a0 = *(const float4*)&As[kk][ty * 8];
            float4 a1 = *(const float4*)&As[kk][ty * 8 + 4];
            const double* b2p = (const double*)&Bs[kk][tx * 8];
            double pb0 = b2p[0], pb1 = b2p[1], pb2 = b2p[2], pb3 = b2p[3];
            double pa[8];
            pa[0] = pack2(a0.x, a0.x); pa[1] = pack2(a0.y, a0.y);
            pa[2] = pack2(a0.z, a0.z); pa[3] = pack2(a0.w, a0.w);
            pa[4] = pack2(a1.x, a1.x); pa[5] = pack2(a1.y, a1.y);
            pa[6] = pack2(a1.z, a1.z); pa[7] = pack2(a1.w, a1.w);
#pragma unroll
            for (int i = 0; i < 8; i++) {
                accp[i][0] = ffma2(pa[i], pb0, accp[i][0]);
                accp[i][1] = ffma2(pa[i], pb1, accp[i][1]);
                accp[i][2] = ffma2(pa[i], pb2, accp[i][2]);
                accp[i][3] = ffma2(pa[i], pb3, accp[i][3]);
            }
        }
        __syncthreads();
    }

    float bv[8], u4v[8], u2v[8];
#pragma unroll
    for (int j = 0; j < 8; j++) {
        bv[j]  = bias[bn + tx * 8 + j];
        u4v[j] = u4[bn + tx * 8 + j];
        u2v[j] = u2[bn + tx * 8 + j];
    }
#pragma unroll
    for (int i = 0; i < 8; i++) {
        int gr = bm + ty * 8 + i;
        if (gr < M) {
            float c[8];
#pragma unroll
            for (int j = 0; j < 4; j++) unpack2(accp[i][j], c[2 * j], c[2 * j + 1]);
            float dv4 = d4[gr], dv2 = d2[gr];
#pragma unroll
            for (int j = 0; j < 8; j++)
                c[j] = c[j] + bv[j] + dv4 * u4v[j] + dv2 * u2v[j];
            *(float4*)&C[(size_t)gr * 256 + bn + tx * 8]     = make_float4(c[0], c[1], c[2], c[3]);
            *(float4*)&C[(size_t)gr * 256 + bn + tx * 8 + 4] = make_float4(c[4], c[5], c[6], c[7]);
        }
    }
}

// ------------------------- column sums -------------------------------------
__global__ void colsum_kernel(const float* __restrict__ h, float* __restrict__ colsum, int n) {
    int f = threadIdx.x;
    int r0 = blockIdx.x * 512;
    int r1 = r0 + 512; if (r1 > n) r1 = n;
    float s = 0.f;
    for (int r = r0; r < r1; r++) s += h[(size_t)r * FD + f];
    atomicAdd(&colsum[f], s);
}

// ------------------------- small 256x256 ops -------------------------------
__global__ void transpose_kernel(const float* __restrict__ A, float* __restrict__ AT) {
    __shared__ float t[32][33];
    int bx = blockIdx.x * 32, by = blockIdx.y * 32;
    t[threadIdx.y][threadIdx.x] = A[(by + threadIdx.y) * FD + bx + threadIdx.x];
    __syncthreads();
    AT[(bx + threadIdx.y) * FD + by + threadIdx.x] = t[threadIdx.x][threadIdx.y];
}

__global__ void nn_kernel(const float* __restrict__ A, const float* __restrict__ B,
                          float* __restrict__ C) {
    __shared__ float a[FD];
    int k = blockIdx.x, j = threadIdx.x;
    a[j] = A[k * FD + j];
    __syncthreads();
    float s = 0.f;
#pragma unroll 8
    for (int p = 0; p < FD; p++) s += a[p] * B[p * FD + j];
    C[k * FD + j] = s;
}

__global__ void rowvec_kernel(const float* __restrict__ W, const float* __restrict__ x,
                              float* __restrict__ y) {
    __shared__ float sx[FD];
    int j = threadIdx.x;
    sx[j] = x[j];
    __syncthreads();
    float s = 0.f;
#pragma unroll 8
    for (int p = 0; p < FD; p++) s += W[j * FD + p] * sx[p];
    y[j] = s;
}

// BN affine from Gram
__global__ void bn_kernel(const float* __restrict__ W1, const float* __restrict__ b1,
                          const float* __restrict__ gamma, const float* __restrict__ beta,
                          const float* __restrict__ Zg, const float* __restrict__ colsum,
                          float* __restrict__ scale, float* __restrict__ cvec, int n) {
    __shared__ double rq[256], rt[256];
    int j = blockIdx.x;
    int p = threadIdx.x;
    double w = (double)W1[j * FD + p];
    rq[p] = w * (double)Zg[p * FD + j];
    rt[p] = w * ((double)colsum[p] / (double)n);
    __syncthreads();
    for (int d = 128; d > 0; d >>= 1) {
        if (p < d) { rq[p] += rq[p + d]; rt[p] += rt[p + d]; }
        __syncthreads();
    }
    if (p == 0) {
        double tm   = rt[0];
        double var  = rq[0] / (double)n - tm * tm;
        double mean = tm + (double)b1[j];
        double sc   = (double)gamma[j] / sqrt(var + 1e-5);
        double sh   = (double)beta[j] - mean * sc;
        scale[j] = (float)sc;
        cvec[j]  = (float)((double)b1[j] * sc + sh);
    }
}

__global__ void scalecols_kernel(const float* __restrict__ P, const float* __restrict__ scale,
                                 float* __restrict__ Ps) {
    int k = blockIdx.x, j = threadIdx.x;
    Ps[k * FD + j] = P[k * FD + j] * scale[j];
}

// ------------------ TN GEMM: out += H1^T @ H2 (split-K, atomics) -----------
__global__ __launch_bounds__(256, 2)
void gemm_tn_kernel(const float* __restrict__ H1, const float* __restrict__ H2,
                    float* __restrict__ out, int M, int chunk) {
    __shared__ float S1[16][132];
    __shared__ float S2[16][68];
    int tid = threadIdx.x;
    int tx = tid & 15, ty = tid >> 4;
    int ba = blockIdx.x * 128;
    int bb = blockIdx.y * 64;
    int k0 = blockIdx.z * chunk;
    int k1 = k0 + chunk; if (k1 > M) k1 = M;

    double accp[8][2];
#pragma unroll
    for (int i = 0; i < 8; i++) { accp[i][0] = 0.0; accp[i][1] = 0.0; }

    for (int k = k0; k < k1; k += 16) {
#pragma unroll
        for (int l = 0; l < 2; l++) {
            int id = l * 256 + tid;
            int row = id >> 5, c = id & 31;
            int gk = k + row;
            float4 v = (gk < k1) ? *(const float4*)&H1[(size_t)gk * FD + ba + c * 4]
                                 : make_float4(0.f, 0.f, 0.f, 0.f);
            *(float4*)&S1[row][c * 4] = v;
        }
        {
            int row = tid >> 4, c = tid & 15;
            int gk = k + row;
            float4 v = (gk < k1) ? *(const float4*)&H2[(size_t)gk * FD + bb + c * 4]
                                 : make_float4(0.f, 0.f, 0.f, 0.f);
            *(float4*)&S2[row][c * 4] = v;
        }
        __syncthreads();
#pragma unroll
        for (int kk = 0; kk < 16; kk++) {
            float4 a0 = *(const float4*)&S1[kk][ty * 8];
            float4 a1 = *(const float4*)&S1[kk][ty * 8 + 4];
            const double* b2p = (const double*)&S2[kk][tx * 4];
            double pb0 = b2p[0], pb1 = b2p[1];
            double pa[8];
            pa[0] = pack2(a0.x, a0.x); pa[1] = pack2(a0.y, a0.y);
            pa[2] = pack2(a0.z, a0.z); pa[3] = pack2(a0.w, a0.w);
            pa[4] = pack2(a1.x, a1.x); pa[5] = pack2(a1.y, a1.y);
            pa[6] = pack2(a1.z, a1.z); pa[7] = pack2(a1.w, a1.w);
#pragma unroll
            for (int i = 0; i < 8; i++) {
                accp[i][0] = ffma2(pa[i], pb0, accp[i][0]);
                accp[i][1] = ffma2(pa[i], pb1, accp[i][1]);
            }
        }
        __syncthreads();
    }
#pragma unroll
    for (int i = 0; i < 8; i++) {
        float c0, c1, c2, c3;
        unpack2(accp[i][0], c0, c1);
        unpack2(accp[i][1], c2, c3);
        float* o = &out[(size_t)(ba + ty * 8 + i) * FD + bb + tx * 4];
        atomicAdd(o + 0, c0);
        atomicAdd(o + 1, c1);
        atomicAdd(o + 2, c2);
        atomicAdd(o + 3, c3);
    }
}

// ------------------------- per-branch pointer bundle -----------------------
struct BranchPtrs {
    int *deg, *rowptr, *offs, *sorted;
    float *A, *B, *tmp, *d2, *d4;
    float *G, *colsum, *scale, *cvec, *Ps, *Q, *Zg, *u4;
};

// ------------------------- orchestration -----------------------------------
extern "C" void kernel_launch(void* const* d_in, const int* in_sizes, int n_in,
                              void* d_out, int out_size) {
    const float* X       = (const float*)d_in[0];
    const int*   srcs[2] = {(const int*)d_in[1], (const int*)d_in[3]};
    const int*   dsts[2] = {(const int*)d_in[2], (const int*)d_in[4]};
    const float* W[3]    = {(const float*)d_in[5], (const float*)d_in[7], (const float*)d_in[9]};
    const float* bias[3] = {(const float*)d_in[6], (const float*)d_in[8], (const float*)d_in[10]};
    const float* gamma   = (const float*)d_in[11];
    const float* beta    = (const float*)d_in[12];
    (void)n_in;

    int n = in_sizes[0] / FD;
    int E = in_sizes[1];
    float* out = (float*)d_out;

    // resolve symbol addresses
    float *pP, *pW1T, *pV3;
    cudaGetSymbolAddress((void**)&pP, g_P);
    cudaGetSymbolAddress((void**)&pW1T, g_W1T);
    cudaGetSymbolAddress((void**)&pV3, g_v3);

    BranchPtrs bp[2];
    {
        int *deg, *rowptr, *offs, *sorted;
        float *A, *B, *tmp, *d2, *d4, *G, *colsum, *scale, *cvec, *Ps, *Q, *Zg, *u4;
        cudaGetSymbolAddress((void**)&deg, g_deg);
        cudaGetSymbolAddress((void**)&rowptr, g_rowptr);
        cudaGetSymbolAddress((void**)&offs, g_offs);
        cudaGetSymbolAddress((void**)&sorted, g_sorted);
        cudaGetSymbolAddress((void**)&A, g_bufA);
        cudaGetSymbolAddress((void**)&B, g_bufB);
        cudaGetSymbolAddress((void**)&tmp, g_tmpv);
        cudaGetSymbolAddress((void**)&d2, g_d2v);
        cudaGetSymbolAddress((void**)&d4, g_d4v);
        cudaGetSymbolAddress((void**)&G, g_G);
        cudaGetSymbolAddress((void**)&colsum, g_colsum);
        cudaGetSymbolAddress((void**)&scale, g_scale);
        cudaGetSymbolAddress((void**)&cvec, g_c);
        cudaGetSymbolAddress((void**)&Ps, g_Ps);
        cudaGetSymbolAddress((void**)&Q, g_Q);
        cudaGetSymbolAddress((void**)&Zg, g_Zg);
        cudaGetSymbolAddress((void**)&u4, g_u4);
        for (int b = 0; b < 2; b++) {
            bp[b].deg = deg + b * NMAX;
            bp[b].rowptr = rowptr + b * (NMAX + 1);
            bp[b].offs = offs + b * NMAX;
            bp[b].sorted = sorted + b * EMAX;
            bp[b].A = A + (size_t)b * NMAX * FD;
            bp[b].B = B + (size_t)b * NMAX * FD;
            bp[b].tmp = tmp + b * NMAX;
            bp[b].d2 = d2 + b * NMAX;
            bp[b].d4 = d4 + b * NMAX;
            bp[b].G = G + b * FD * FD;
            bp[b].colsum = colsum + b * FD;
            bp[b].scale = scale + b * FD;
            bp[b].cvec = cvec + b * FD;
            bp[b].Ps = Ps + b * FD * FD;
            bp[b].Q = Q + b * FD * FD;
            bp[b].Zg = Zg + b * FD * FD;
            bp[b].u4 = u4 + b * FD;
        }
    }

    // streams / events (created once; handles only, no device memory)
    static cudaStream_t s1 = nullptr;
    static cudaEvent_t eFork = nullptr, eJoin = nullptr;
    if (!s1) {
        cudaStreamCreateWithFlags(&s1, cudaStreamNonBlocking);
        cudaEventCreateWithFlags(&eFork, cudaEventDisableTiming);
        cudaEventCreateWithFlags(&eJoin, cudaEventDisableTiming);
    }

    dim3 spmmBlock(32, 8);
    int  spmmGrid = (n + 7) / 8;
    int  eGrid = (E + 255) / 256;
    int  nGrid256 = (n + 255) / 256;
    int  redGrid = (n + 511) / 512;
    dim3 ntGrid((n + 127) / 128, FD / 128);
    int  chunk = 2048;
    dim3 tnGrid(FD / 128, FD / 64, (n + chunk - 1) / chunk);
    dim3 tpGrid(FD / 32, FD / 32), tpBlock(32, 32);

    // shared precompute on capture stream
    nn_kernel<<<FD, FD>>>(W[2], W[1], pP);
    rowvec_kernel<<<1, FD>>>(W[2], bias[1], pV3);
    transpose_kernel<<<tpGrid, tpBlock>>>(W[0], pW1T);

    // fork branch 1 onto s1
    cudaEventRecord(eFork, 0);
    cudaStreamWaitEvent(s1, eFork, 0);

    for (int br = 0; br < 2; ++br) {
        cudaStream_t st = (br == 0) ? (cudaStream_t)0 : s1;
        BranchPtrs& p = bp[br];

        // CSR build (counting sort by dst)
        cudaMemsetAsync(p.deg, 0, n * sizeof(int), st);
        hist_kernel<<<eGrid, 256, 0, st>>>(p.deg, dsts[br], E);
        scan_kernel<<<1, 1024, 0, st>>>(p.deg, p.rowptr, p.offs, n);
        scatter_kernel<<<eGrid, 256, 0, st>>>(p.offs, p.sorted, srcs[br], dsts[br], E);

        // d2 = A^2 1 ; d4 = A^4 1
        spmv_deg_kernel<<<nGrid256, 256, 0, st>>>(p.rowptr, p.sorted, p.d2, n);
        spmv_kernel<<<nGrid256, 256, 0, st>>>(p.rowptr, p.sorted, p.d2, p.tmp, n);
        spmv_kernel<<<nGrid256, 256, 0, st>>>(p.rowptr, p.sorted, p.tmp, p.d4, n);

        // Z2 = A^2 X
        spmm_kernel<<<spmmGrid, spmmBlock, 0, st>>>(p.rowptr, p.sorted, X, p.A, n);
        spmm_kernel<<<spmmGrid, spmmBlock, 0, st>>>(p.rowptr, p.sorted, p.A, p.B, n);

        // stats of Z2: column sums + Gram
        cudaMemsetAsync(p.colsum, 0, FD * sizeof(float), st);
        colsum_kernel<<<redGrid, 256, 0, st>>>(p.B, p.colsum, n);
        cudaMemsetAsync(p.G, 0, FD * FD * sizeof(float), st);
        gemm_tn_kernel<<<tnGrid, 256, 0, st>>>(p.B, p.B, p.G, n, chunk);

        // BN affine coefficients from Gram
        nn_kernel<<<FD, FD, 0, st>>>(p.G, pW1T, p.Zg);
        bn_kernel<<<FD, FD, 0, st>>>(W[0], bias[0], gamma, beta, p.Zg, p.colsum,
                                     p.scale, p.cvec, n);

        // Q = P diag(s) W1 ; u4 = P c
        scalecols_kernel<<<FD, FD, 0, st>>>(pP, p.scale, p.Ps);
        nn_kernel<<<FD, FD, 0, st>>>(p.Ps, W[0], p.Q);
        rowvec_kernel<<<1, FD, 0, st>>>(pP, p.cvec, p.u4);

        // Z6 = A^4 Z2
        spmm_kernel<<<spmmGrid, spmmBlock, 0, st>>>(p.rowptr, p.sorted, p.B, p.A, n);
        spmm_kernel<<<spmmGrid, spmmBlock, 0, st>>>(p.rowptr, p.sorted, p.A, p.B, n);
        spmm_kernel<<<spmmGrid, spmmBlock, 0, st>>>(p.rowptr, p.sorted, p.B, p.A, n);
        spmm_kernel<<<spmmGrid, spmmBlock, 0, st>>>(p.rowptr, p.sorted, p.A, p.B, n);

        // h3 = Z6 Q^T + d4 u4^T + d2 v3^T + b3   (into p.A)
        gemm_nt2_kernel<<<ntGrid, 256, 0, st>>>(p.B, p.Q, bias[2], p.d4, p.u4,
                                                p.d2, pV3, p.A, n);
    }

    // join branch 1 back into capture stream
    cudaEventRecord(eJoin, s1);
    cudaStreamWaitEvent(0, eJoin, 0);

    // out = h3a^T @ h3b
    cudaMemsetAsync(out, 0, (size_t)out_size * sizeof(float));
    gemm_tn_kernel<<<tnGrid, 256>>>(bp[0].A, bp[1].A, out, n, chunk);
}

// round 13
// speedup vs baseline: 1.1832x; 1.0481x over previous
#include <cuda_runtime.h>
#include <math.h>

#define FD 256
#define NMAX 50048
#define EMAX 800000

// ------------------------- scratch (device globals, per-branch) ------------
__device__ float  g_bufA[2][NMAX * FD];
__device__ float  g_bufB[2][NMAX * FD];
__device__ int    g_deg[2][NMAX];
__device__ int    g_rowptr[2][NMAX + 1];
__device__ int    g_offs[2][NMAX];
__device__ int    g_sorted[2][EMAX];

__device__ float  g_tmpv[2][NMAX];
__device__ float  g_d2v[2][NMAX];
__device__ float  g_d4v[2][NMAX];

__device__ float  g_G[2][FD * FD];
__device__ float  g_colsum[2][FD];
__device__ float  g_scale[2][FD];
__device__ float  g_c[2][FD];
__device__ float  g_Ps[2][FD * FD];
__device__ float  g_Q[2][FD * FD];
__device__ float  g_Zg[2][FD * FD];
__device__ float  g_u4[2][FD];

// shared
__device__ float  g_P[FD * FD];             // W3 @ W2
__device__ float  g_W1T[FD * FD];
__device__ float  g_v3[FD];                 // W3 @ b2

// ------------------------- packed f32x2 helpers ----------------------------
__device__ __forceinline__ double pack2(float lo, float hi) {
    double d;
    asm("mov.b64 %0, {%1, %2};" : "=d"(d) : "f"(lo), "f"(hi));
    return d;
}
__device__ __forceinline__ void unpack2(double d, float& lo, float& hi) {
    asm("mov.b64 {%0, %1}, %2;" : "=f"(lo), "=f"(hi) : "d"(d));
}
__device__ __forceinline__ double ffma2(double a, double b, double c) {
    double d;
    asm("fma.rn.f32x2 %0, %1, %2, %3;" : "=d"(d) : "d"(a), "d"(b), "d"(c));
    return d;
}

// ------------------------- CSR construction -------------------------------
__global__ void hist_kernel(int* __restrict__ deg, const int* __restrict__ dst, int E) {
    int e = blockIdx.x * blockDim.x + threadIdx.x;
    if (e < E) atomicAdd(&deg[dst[e]], 1);
}

__global__ void scan_kernel(const int* __restrict__ deg, int* __restrict__ rowptr,
                            int* __restrict__ offs, int n) {
    __shared__ int s[1024];
    int t = threadIdx.x;
    int chunk = (n + 1023) >> 10;
    int lo = t * chunk; if (lo > n) lo = n;
    int hi = lo + chunk; if (hi > n) hi = n;
    int sum = 0;
    for (int i = lo; i < hi; i++) sum += deg[i];
    s[t] = sum;
    __syncthreads();
    for (int d = 1; d < 1024; d <<= 1) {
        int v = (t >= d) ? s[t - d] : 0;
        __syncthreads();
        s[t] += v;
        __syncthreads();
    }
    int run = s[t] - sum;
    for (int i = lo; i < hi; i++) {
        rowptr[i] = run;
        offs[i]   = run;
        run += deg[i];
    }
    if (t == 1023) rowptr[n] = s[1023];
}

__global__ void scatter_kernel(int* __restrict__ offs, int* __restrict__ sorted,
                               const int* __restrict__ src, const int* __restrict__ dst, int E) {
    int e = blockIdx.x * blockDim.x + threadIdx.x;
    if (e < E) {
        int p = atomicAdd(&offs[dst[e]], 1);
        sorted[p] = src[e];
    }
}

// ------------------------- SpMV chain (d vectors) --------------------------
__global__ void spmv_deg_kernel(const int* __restrict__ rowptr, const int* __restrict__ sorted,
                                float* __restrict__ y, int n) {
    int i = blockIdx.x * blockDim.x + threadIdx.x;
    if (i >= n) return;
    int s = rowptr[i], e = rowptr[i + 1];
    float acc = 0.f;
    for (int k = s; k < e; k++) {
        int u = sorted[k];
        acc += (float)(rowptr[u + 1] - rowptr[u]);
    }
    y[i] = acc;
}

__global__ void spmv_kernel(const int* __restrict__ rowptr, const int* __restrict__ sorted,
                            const float* __restrict__ x, float* __restrict__ y, int n) {
    int i = blockIdx.x * blockDim.x + threadIdx.x;
    if (i >= n) return;
    int s = rowptr[i], e = rowptr[i + 1];
    float acc = 0.f;
    for (int k = s; k < e; k++) acc += x[sorted[k]];
    y[i] = acc;
}

// ------------------------- SpMM (pull, CSR, warp per node) -----------------
// block = (32, 8): one warp per node, each lane owns 8 features (2 float4)
// 8-edge unroll (16 outstanding LDG.128 per lane), L1 caching kept (__ldg)
__global__ void spmm_kernel(const int* __restrict__ rowptr, const int* __restrict__ sorted,
                            const float* __restrict__ h, float* __restrict__ out, int n) {
    int lane = threadIdx.x;
    int node = blockIdx.x * 8 + threadIdx.y;
    if (node >= n) return;
    int s = rowptr[node];
    int e = rowptr[node + 1];
    const float4* hp = (const float4*)h;
    float4 acc0 = make_float4(0.f, 0.f, 0.f, 0.f);
    float4 acc1 = make_float4(0.f, 0.f, 0.f, 0.f);
    int i = s;
    for (; i + 8 <= e; i += 8) {
        int u[8];
#pragma unroll
        for (int t = 0; t < 8; t++) u[t] = __ldg(&sorted[i + t]);
        float4 va[8], vb[8];
#pragma unroll
        for (int t = 0; t < 8; t++) {
            va[t] = __ldg(&hp[(size_t)u[t] * 64 + lane]);
            vb[t] = __ldg(&hp[(size_t)u[t] * 64 + 32 + lane]);
        }
#pragma unroll
        for (int t = 0; t < 8; t++) {
            acc0.x += va[t].x; acc0.y += va[t].y; acc0.z += va[t].z; acc0.w += va[t].w;
            acc1.x += vb[t].x; acc1.y += vb[t].y; acc1.z += vb[t].z; acc1.w += vb[t].w;
        }
    }
    if (i + 4 <= e) {
        int u[4];
#pragma unroll
        for (int t = 0; t < 4; t++) u[t] = __ldg(&sorted[i + t]);
        float4 va[4], vb[4];
#pragma unroll
        for (int t = 0; t < 4; t++) {
            va[t] = __ldg(&hp[(size_t)u[t] * 64 + lane]);
            vb[t] = __ldg(&hp[(size_t)u[t] * 64 + 32 + lane]);
        }
#pragma unroll
        for (int t = 0; t < 4; t++) {
            acc0.x += va[t].x; acc0.y += va[t].y; acc0.z += va[t].z; acc0.w += va[t].w;
            acc1.x += vb[t].x; acc1.y += vb[t].y; acc1.z += vb[t].z; acc1.w += vb[t].w;
        }
        i += 4;
    }
    for (; i < e; i++) {
        int u = __ldg(&sorted[i]);
        float4 a = __ldg(&hp[(size_t)u * 64 + lane]);
        float4 b = __ldg(&hp[(size_t)u * 64 + 32 + lane]);
        acc0.x += a.x; acc0.y += a.y; acc0.z += a.z; acc0.w += a.w;
        acc1.x += b.x; acc1.y += b.y; acc1.z += b.z; acc1.w += b.w;
    }
    float4* op = (float4*)&out[(size_t)node * FD];
    op[lane]      = acc0;
    op[lane + 32] = acc1;
}

// --------- NT GEMM: C = H @ W^T + bias + d4*u4^T + d2*u2^T -----------------
__global__ __launch_bounds__(256, 2)
void gemm_nt2_kernel(const float* __restrict__ H, const float* __restrict__ W,
                     const float* __restrict__ bias,
                     const float* __restrict__ d4, const float* __restrict__ u4,
                     const float* __restrict__ d2, const float* __restrict__ u2,
                     float* __restrict__ C, int M) {
    __shared__ float As[16][132];
    __shared__ float Bs[16][132];
    int tid = threadIdx.x;
    int tx = tid & 15;
    int ty = tid >> 4;
    int bm = blockIdx.x * 128;
    int bn = blockIdx.y * 128;

    double accp[8][4];
#pragma unroll
    for (int i = 0; i < 8; i++)
#pragma unroll
        for (int j = 0; j < 4; j++) accp[i][j] = 0.0;

    for (int k0 = 0; k0 < 256; k0 += 16) {
#pragma unroll
        for (int l = 0; l < 2; l++) {
            int id = l * 256 + tid;
            int row = id >> 2, c4 = id & 3;
            int gr = bm + row;
            float4 v = (gr < M) ? *(const float4*)&H[(size_t)gr * 256 + k0 + c4 * 4]
                                : make_float4(0.f, 0.f, 0.f, 0.f);
            As[c4 * 4 + 0][row] = v.x;
            As[c4 * 4 + 1][row] = v.y;
            As[c4 * 4 + 2][row] = v.z;
            As[c4 * 4 + 3][row] = v.w;
        }
#pragma unroll
        for (int l = 0; l < 2; l++) {
            int id = l * 256 + tid;
            int row = id >> 2, c4 = id & 3;
            float4 v = *(const float4*)&W[(size_t)(bn + row) * 256 + k0 + c4 * 4];
            Bs[c4 * 4 + 0][row] = v.x;
            Bs[c4 * 4 + 1][row] = v.y;
            Bs[c4 * 4 + 2][row] = v.z;
            Bs[c4 * 4 + 3][row] = v.w;
        }
        __syncthreads();
#pragma unroll
        for (int kk = 0; kk < 16; kk++) {
            float4 a0 = *(const float4*)&As[kk][ty * 8];
            float4 a1 = *(const float4*)&As[kk][ty * 8 + 4];
            const double* b2p = (const double*)&Bs[kk][tx * 8];
            double pb0 = b2p[0], pb1 = b2p[1], pb2 = b2p[2], pb3 = b2p[3];
            double pa[8];
            pa[0] = pack2(a0.x, a0.x); pa[1] = pack2(a0.y, a0.y);
            pa[2] = pack2(a0.z, a0.z); pa[3] = pack2(a0.w, a0.w);
            pa[4] = pack2(a1.x, a1.x); pa[5] = pack2(a1.y, a1.y);
            pa[6] = pack2(a1.z, a1.z); pa[7] = pack2(a1.w, a1.w);
#pragma unroll
            for (int i = 0; i < 8; i++) {
                accp[i][0] = ffma2(pa[i], pb0, accp[i][0]);
                accp[i][1] = ffma2(pa[i], pb1, accp[i][1]);
                accp[i][2] = ffma2(pa[i], pb2, accp[i][2]);
                accp[i][3] = ffma2(pa[i], pb3, accp[i][3]);
            }
        }
        __syncthreads();
    }

    float bv[8], u4v[8], u2v[8];
#pragma unroll
    for (int j = 0; j < 8; j++) {
        bv[j]  = bias[bn + tx * 8 + j];
        u4v[j] = u4[bn + tx * 8 + j];
        u2v[j] = u2[bn + tx * 8 + j];
    }
#pragma unroll
    for (int i = 0; i < 8; i++) {
        int gr = bm + ty * 8 + i;
        if (gr < M) {
            float c[8];
#pragma unroll
            for (int j = 0; j < 4; j++) unpack2(accp[i][j], c[2 * j], c[2 * j + 1]);
            float dv4 = d4[gr], dv2 = d2[gr];
#pragma unroll
            for (int j = 0; j < 8; j++)
                c[j] = c[j] + bv[j] + dv4 * u4v[j] + dv2 * u2v[j];
            *(float4*)&C[(size_t)gr * 256 + bn + tx * 8]     = make_float4(c[0], c[1], c[2], c[3]);
            *(float4*)&C[(size_t)gr * 256 + bn + tx * 8 + 4] = make_float4(c[4], c[5], c[6], c[7]);
        }
    }
}

// ------------------------- column sums -------------------------------------
__global__ void colsum_kernel(const float* __restrict__ h, float* __restrict__ colsum, int n) {
    int f = threadIdx.x;
    int r0 = blockIdx.x * 512;
    int r1 = r0 + 512; if (r1 > n) r1 = n;
    float s = 0.f;
    for (int r = r0; r < r1; r++) s += h[(size_t)r * FD + f];
    atomicAdd(&colsum[f], s);
}

// ------------------------- small 256x256 ops -------------------------------
__global__ void transpose_kernel(const float* __restrict__ A, float* __restrict__ AT) {
    __shared__ float t[32][33];
    int bx = blockIdx.x * 32, by = blockIdx.y * 32;
    t[threadIdx.y][threadIdx.x] = A[(by + threadIdx.y) * FD + bx + threadIdx.x];
    __syncthreads();
    AT[(bx + threadIdx.y) * FD + by + threadIdx.x] = t[threadIdx.x][threadIdx.y];
}

__global__ void nn_kernel(const float* __restrict__ A, const float* __restrict__ B,
                          float* __restrict__ C) {
    __shared__ float a[FD];
    int k = blockIdx.x, j = threadIdx.x;
    a[j] = A[k * FD + j];
    __syncthreads();
    float s = 0.f;
#pragma unroll 8
    for (int p = 0; p < FD; p++) s += a[p] * B[p * FD + j];
    C[k * FD + j] = s;
}

__global__ void rowvec_kernel(const float* __restrict__ W, const float* __restrict__ x,
                              float* __restrict__ y) {
    __shared__ float sx[FD];
    int j = threadIdx.x;
    sx[j] = x[j];
    __syncthreads();
    float s = 0.f;
#pragma unroll 8
    for (int p = 0; p < FD; p++) s += W[j * FD + p] * sx[p];
    y[j] = s;
}

// BN affine from Gram
__global__ void bn_kernel(const float* __restrict__ W1, const float* __restrict__ b1,
                          const float* __restrict__ gamma, const float* __restrict__ beta,
                          const float* __restrict__ Zg, const float* __restrict__ colsum,
                          float* __restrict__ scale, float* __restrict__ cvec, int n) {
    __shared__ double rq[256], rt[256];
    int j = blockIdx.x;
    int p = threadIdx.x;
    double w = (double)W1[j * FD + p];
    rq[p] = w * (double)Zg[p * FD + j];
    rt[p] = w * ((double)colsum[p] / (double)n);
    __syncthreads();
    for (int d = 128; d > 0; d >>= 1) {
        if (p < d) { rq[p] += rq[p + d]; rt[p] += rt[p + d]; }
        __syncthreads();
    }
    if (p == 0) {
        double tm   = rt[0];
        double var  = rq[0] / (double)n - tm * tm;
        double mean = tm + (double)b1[j];
        double sc   = (double)gamma[j] / sqrt(var + 1e-5);
        double sh   = (double)beta[j] - mean * sc;
        scale[j] = (float)sc;
        cvec[j]  = (float)((double)b1[j] * sc + sh);
    }
}

__global__ void scalecols_kernel(const float* __restrict__ P, const float* __restrict__ scale,
                                 float* __restrict__ Ps) {
    int k = blockIdx.x, j = threadIdx.x;
    Ps[k * FD + j] = P[k * FD + j] * scale[j];
}

// ------------------ TN GEMM: out += H1^T @ H2 (split-K, atomics) -----------
__global__ __launch_bounds__(256, 2)
void gemm_tn_kernel(const float* __restrict__ H1, const float* __restrict__ H2,
                    float* __restrict__ out, int M, int chunk) {
    __shared__ float S1[16][132];
    __shared__ float S2[16][68];
    int tid = threadIdx.x;
    int tx = tid & 15, ty = tid >> 4;
    int ba = blockIdx.x * 128;
    int bb = blockIdx.y * 64;
    int k0 = blockIdx.z * chunk;
    int k1 = k0 + chunk; if (k1 > M) k1 = M;

    double accp[8][2];
#pragma unroll
    for (int i = 0; i < 8; i++) { accp[i][0] = 0.0; accp[i][1] = 0.0; }

    for (int k = k0; k < k1; k += 16) {
#pragma unroll
        for (int l = 0; l < 2; l++) {
            int id = l * 256 + tid;
            int row = id >> 5, c = id & 31;
            int gk = k + row;
            float4 v = (gk < k1) ? *(const float4*)&H1[(size_t)gk * FD + ba + c * 4]
                                 : make_float4(0.f, 0.f, 0.f, 0.f);
            *(float4*)&S1[row][c * 4] = v;
        }
        {
            int row = tid >> 4, c = tid & 15;
            int gk = k + row;
            float4 v = (gk < k1) ? *(const float4*)&H2[(size_t)gk * FD + bb + c * 4]
                                 : make_float4(0.f, 0.f, 0.f, 0.f);
            *(float4*)&S2[row][c * 4] = v;
        }
        __syncthreads();
#pragma unroll
        for (int kk = 0; kk < 16; kk++) {
            float4 a0 = *(const float4*)&S1[kk][ty * 8];
            float4 a1 = *(const float4*)&S1[kk][ty * 8 + 4];
            const double* b2p = (const double*)&S2[kk][tx * 4];
            double pb0 = b2p[0], pb1 = b2p[1];
            double pa[8];
            pa[0] = pack2(a0.x, a0.x); pa[1] = pack2(a0.y, a0.y);
            pa[2] = pack2(a0.z, a0.z); pa[3] = pack2(a0.w, a0.w);
            pa[4] = pack2(a1.x, a1.x); pa[5] = pack2(a1.y, a1.y);
            pa[6] = pack2(a1.z, a1.z); pa[7] = pack2(a1.w, a1.w);
#pragma unroll
            for (int i = 0; i < 8; i++) {
                accp[i][0] = ffma2(pa[i], pb0, accp[i][0]);
                accp[i][1] = ffma2(pa[i], pb1, accp[i][1]);
            }
        }
        __syncthreads();
    }
#pragma unroll
    for (int i = 0; i < 8; i++) {
        float c0, c1, c2, c3;
        unpack2(accp[i][0], c0, c1);
        unpack2(accp[i][1], c2, c3);
        float* o = &out[(size_t)(ba + ty * 8 + i) * FD + bb + tx * 4];
        atomicAdd(o + 0, c0);
        atomicAdd(o + 1, c1);
        atomicAdd(o + 2, c2);
        atomicAdd(o + 3, c3);
    }
}

// ------------------------- per-branch pointer bundle -----------------------
struct BranchPtrs {
    int *deg, *rowptr, *offs, *sorted;
    float *A, *B, *tmp, *d2, *d4;
    float *G, *colsum, *scale, *cvec, *Ps, *Q, *Zg, *u4;
};

// ------------------------- orchestration -----------------------------------
extern "C" void kernel_launch(void* const* d_in, const int* in_sizes, int n_in,
                              void* d_out, int out_size) {
    const float* X       = (const float*)d_in[0];
    const int*   srcs[2] = {(const int*)d_in[1], (const int*)d_in[3]};
    const int*   dsts[2] = {(const int*)d_in[2], (const int*)d_in[4]};
    const float* W[3]    = {(const float*)d_in[5], (const float*)d_in[7], (const float*)d_in[9]};
    const float* bias[3] = {(const float*)d_in[6], (const float*)d_in[8], (const float*)d_in[10]};
    const float* gamma   = (const float*)d_in[11];
    const float* beta    = (const float*)d_in[12];
    (void)n_in;

    int n = in_sizes[0] / FD;
    int E = in_sizes[1];
    float* out = (float*)d_out;

    // resolve symbol addresses
    float *pP, *pW1T, *pV3;
    cudaGetSymbolAddress((void**)&pP, g_P);
    cudaGetSymbolAddress((void**)&pW1T, g_W1T);
    cudaGetSymbolAddress((void**)&pV3, g_v3);

    BranchPtrs bp[2];
    {
        int *deg, *rowptr, *offs, *sorted;
        float *A, *B, *tmp, *d2, *d4, *G, *colsum, *scale, *cvec, *Ps, *Q, *Zg, *u4;
        cudaGetSymbolAddress((void**)&deg, g_deg);
        cudaGetSymbolAddress((void**)&rowptr, g_rowptr);
        cudaGetSymbolAddress((void**)&offs, g_offs);
        cudaGetSymbolAddress((void**)&sorted, g_sorted);
        cudaGetSymbolAddress((void**)&A, g_bufA);
        cudaGetSymbolAddress((void**)&B, g_bufB);
        cudaGetSymbolAddress((void**)&tmp, g_tmpv);
        cudaGetSymbolAddress((void**)&d2, g_d2v);
        cudaGetSymbolAddress((void**)&d4, g_d4v);
        cudaGetSymbolAddress((void**)&G, g_G);
        cudaGetSymbolAddress((void**)&colsum, g_colsum);
        cudaGetSymbolAddress((void**)&scale, g_scale);
        cudaGetSymbolAddress((void**)&cvec, g_c);
        cudaGetSymbolAddress((void**)&Ps, g_Ps);
        cudaGetSymbolAddress((void**)&Q, g_Q);
        cudaGetSymbolAddress((void**)&Zg, g_Zg);
        cudaGetSymbolAddress((void**)&u4, g_u4);
        for (int b = 0; b < 2; b++) {
            bp[b].deg = deg + b * NMAX;
            bp[b].rowptr = rowptr + b * (NMAX + 1);
            bp[b].offs = offs + b * NMAX;
            bp[b].sorted = sorted + b * EMAX;
            bp[b].A = A + (size_t)b * NMAX * FD;
            bp[b].B = B + (size_t)b * NMAX * FD;
            bp[b].tmp = tmp + b * NMAX;
            bp[b].d2 = d2 + b * NMAX;
            bp[b].d4 = d4 + b * NMAX;
            bp[b].G = G + b * FD * FD;
            bp[b].colsum = colsum + b * FD;
            bp[b].scale = scale + b * FD;
            bp[b].cvec = cvec + b * FD;
            bp[b].Ps = Ps + b * FD * FD;
            bp[b].Q = Q + b * FD * FD;
            bp[b].Zg = Zg + b * FD * FD;
            bp[b].u4 = u4 + b * FD;
        }
    }

    // streams / events (created once; handles only, no device memory)
    static cudaStream_t s1 = nullptr;
    static cudaEvent_t eFork = nullptr, eJoin = nullptr;
    if (!s1) {
        cudaStreamCreateWithFlags(&s1, cudaStreamNonBlocking);
        cudaEventCreateWithFlags(&eFork, cudaEventDisableTiming);
        cudaEventCreateWithFlags(&eJoin, cudaEventDisableTiming);
    }

    dim3 spmmBlock(32, 8);
    int  spmmGrid = (n + 7) / 8;
    int  eGrid = (E + 255) / 256;
    int  nGrid256 = (n + 255) / 256;
    int  redGrid = (n + 511) / 512;
    dim3 ntGrid((n + 127) / 128, FD / 128);
    int  chunk = 1024;
    dim3 tnGrid(FD / 128, FD / 64, (n + chunk - 1) / chunk);
    dim3 tpGrid(FD / 32, FD / 32), tpBlock(32, 32);

    // shared precompute on capture stream
    nn_kernel<<<FD, FD>>>(W[2], W[1], pP);
    rowvec_kernel<<<1, FD>>>(W[2], bias[1], pV3);
    transpose_kernel<<<tpGrid, tpBlock>>>(W[0], pW1T);

    // fork branch 1 onto s1
    cudaEventRecord(eFork, 0);
    cudaStreamWaitEvent(s1, eFork, 0);

    for (int br = 0; br < 2; ++br) {
        cudaStream_t st = (br == 0) ? (cudaStream_t)0 : s1;
        BranchPtrs& p = bp[br];

        // CSR build (counting sort by dst)
        cudaMemsetAsync(p.deg, 0, n * sizeof(int), st);
        hist_kernel<<<eGrid, 256, 0, st>>>(p.deg, dsts[br], E);
        scan_kernel<<<1, 1024, 0, st>>>(p.deg, p.rowptr, p.offs, n);
        scatter_kernel<<<eGrid, 256, 0, st>>>(p.offs, p.sorted, srcs[br], dsts[br], E);

        // d2 = A^2 1 ; d4 = A^4 1
        spmv_deg_kernel<<<nGrid256, 256, 0, st>>>(p.rowptr, p.sorted, p.d2, n);
        spmv_kernel<<<nGrid256, 256, 0, st>>>(p.rowptr, p.sorted, p.d2, p.tmp, n);
        spmv_kernel<<<nGrid256, 256, 0, st>>>(p.rowptr, p.sorted, p.tmp, p.d4, n);

        // Z2 = A^2 X
        spmm_kernel<<<spmmGrid, spmmBlock, 0, st>>>(p.rowptr, p.sorted, X, p.A, n);
        spmm_kernel<<<spmmGrid, spmmBlock, 0, st>>>(p.rowptr, p.sorted, p.A, p.B, n);

        // stats of Z2: column sums + Gram
        cudaMemsetAsync(p.colsum, 0, FD * sizeof(float), st);
        colsum_kernel<<<redGrid, 256, 0, st>>>(p.B, p.colsum, n);
        cudaMemsetAsync(p.G, 0, FD * FD * sizeof(float), st);
        gemm_tn_kernel<<<tnGrid, 256, 0, st>>>(p.B, p.B, p.G, n, chunk);

        // BN affine coefficients from Gram
        nn_kernel<<<FD, FD, 0, st>>>(p.G, pW1T, p.Zg);
        bn_kernel<<<FD, FD, 0, st>>>(W[0], bias[0], gamma, beta, p.Zg, p.colsum,
                                     p.scale, p.cvec, n);

        // Q = P diag(s) W1 ; u4 = P c
        scalecols_kernel<<<FD, FD, 0, st>>>(pP, p.scale, p.Ps);
        nn_kernel<<<FD, FD, 0, st>>>(p.Ps, W[0], p.Q);
        rowvec_kernel<<<1, FD, 0, st>>>(pP, p.cvec, p.u4);

        // Z6 = A^4 Z2
        spmm_kernel<<<spmmGrid, spmmBlock, 0, st>>>(p.rowptr, p.sorted, p.B, p.A, n);
        spmm_kernel<<<spmmGrid, spmmBlock, 0, st>>>(p.rowptr, p.sorted, p.A, p.B, n);
        spmm_kernel<<<spmmGrid, spmmBlock, 0, st>>>(p.rowptr, p.sorted, p.B, p.A, n);
        spmm_kernel<<<spmmGrid, spmmBlock, 0, st>>>(p.rowptr, p.sorted, p.A, p.B, n);

        // h3 = Z6 Q^T + d4 u4^T + d2 v3^T + b3   (into p.A)
        gemm_nt2_kernel<<<ntGrid, 256, 0, st>>>(p.B, p.Q, bias[2], p.d4, p.u4,
                                                p.d2, pV3, p.A, n);
    }

    // join branch 1 back into capture stream
    cudaEventRecord(eJoin, s1);
    cudaStreamWaitEvent(0, eJoin, 0);

    // out = h3a^T @ h3b
    cudaMemsetAsync(out, 0, (size_t)out_size * sizeof(float));
    gemm_tn_kernel<<<tnGrid, 256>>>(bp[0].A, bp[1].A, out, n, chunk);
}